// round 4
// baseline (speedup 1.0000x reference)
#include <cuda_runtime.h>
#include <cuda_bf16.h>
#include <math.h>

#define N_NODES_ 20000
#define N_EDGES_ 160000
#define DIM 512
#define N_GRAPHS_ 128

// ---------------- scratch (device globals; referenced ONLY in device code) ---
__device__ float g_h[N_NODES_ * DIM];     // GEMM output / message source
__device__ float g_y[N_NODES_ * DIM];     // conv output / activations
__device__ float g_colsum[DIM];
__device__ float g_colsq[DIM];
__device__ float g_mu[DIM];
__device__ float g_isd[DIM];
__device__ int   g_deg[N_NODES_];         // 1 (self) + in-degree
__device__ float g_dis[N_NODES_];         // deg^{-1/2}
__device__ int   g_off[N_NODES_];         // CSR offsets (in-edges, excl. self)
__device__ int   g_cur[N_NODES_];         // fill cursors
__device__ int   g_csrc[N_EDGES_];        // CSR: source node per in-edge
__device__ float g_cnorm[N_EDGES_];       // CSR: dis[src]*dis[dst]
__device__ float g_pool[N_GRAPHS_ * DIM]; // pooled means
__device__ int   g_cnt[N_GRAPHS_];
__device__ int   g_goff[N_GRAPHS_];       // graph start row (batch is sorted)
__device__ int   g_is64;                  // 1 if index inputs are int64

// ---------------- dtype detection (int64 vs int32 indices) -------------------
__global__ void detect_kernel(const int* __restrict__ ei32) {
    if (threadIdx.x == 0 && blockIdx.x == 0) {
        int all_hi_zero = 1;
        #pragma unroll
        for (int i = 0; i < 16; i++) all_hi_zero &= (ei32[2 * i + 1] == 0);
        g_is64 = all_hi_zero;
    }
}

__device__ __forceinline__ int load_idx(const void* p, int e) {
    if (g_is64) return (int)((const long long*)p)[e];
    return ((const int*)p)[e];
}

// ---------------- init --------------------------------------------------------
__global__ void init_kernel() {
    int i = blockIdx.x * blockDim.x + threadIdx.x;
    if (i < N_NODES_) { g_deg[i] = 1; g_cur[i] = 0; }
    if (i < DIM)      { g_colsum[i] = 0.f; g_colsq[i] = 0.f; }
    if (i < N_GRAPHS_)  g_cnt[i] = 0;
}

// ---------------- column mean / std (population) -----------------------------
#define ROWS_PER_BLOCK 100
__global__ void col_stats(const float* __restrict__ x) {
    int t = threadIdx.x;               // 256 threads
    int c0 = t, c1 = t + 256;
    float s0 = 0.f, s1 = 0.f, q0 = 0.f, q1 = 0.f;
    int r0 = blockIdx.x * ROWS_PER_BLOCK;
    int r1 = min(r0 + ROWS_PER_BLOCK, N_NODES_);
    for (int r = r0; r < r1; r++) {
        float v0 = x[(size_t)r * DIM + c0];
        float v1 = x[(size_t)r * DIM + c1];
        s0 += v0; q0 += v0 * v0;
        s1 += v1; q1 += v1 * v1;
    }
    atomicAdd(&g_colsum[c0], s0); atomicAdd(&g_colsq[c0], q0);
    atomicAdd(&g_colsum[c1], s1); atomicAdd(&g_colsq[c1], q1);
}

__global__ void finalize_stats() {
    int j = blockIdx.x * blockDim.x + threadIdx.x;
    if (j >= DIM) return;
    float mean = g_colsum[j] * (1.f / (float)N_NODES_);
    float var  = g_colsq[j] * (1.f / (float)N_NODES_) - mean * mean;
    float sd   = sqrtf(fmaxf(var, 0.f));
    g_mu[j]  = mean;
    g_isd[j] = (sd > 0.f) ? (1.f / sd) : 1.f;
}

// ---------------- degree / normalization / batch histogram -------------------
// dst element index = N_EDGES_ + e inside the [2,E] edge buffer (works for
// both int32 and int64 layouts).
__global__ void degree_kernel(const void* __restrict__ ei,
                              const void* __restrict__ batch) {
    int e = blockIdx.x * blockDim.x + threadIdx.x;
    if (e < N_EDGES_) {
        int d = load_idx(ei, N_EDGES_ + e);
        if (d >= 0 && d < N_NODES_) atomicAdd(&g_deg[d], 1);
    }
    if (e < N_NODES_) {
        int g = load_idx(batch, e);
        if (g >= 0 && g < N_GRAPHS_) atomicAdd(&g_cnt[g], 1);
    }
}

__global__ void dis_kernel() {
    int i = blockIdx.x * blockDim.x + threadIdx.x;
    if (i < N_NODES_) g_dis[i] = rsqrtf((float)g_deg[i]);
}

// ---------------- exclusive prefix scan over in-edge counts (1 block) --------
__global__ __launch_bounds__(1024)
void scan_kernel() {
    __shared__ int part[1024];
    int t = threadIdx.x;
    const int CH = (N_NODES_ + 1023) / 1024;   // 20
    int b0 = t * CH, b1 = min(b0 + CH, N_NODES_);
    int s = 0;
    for (int i = b0; i < b1; i++) s += g_deg[i] - 1;
    part[t] = s;
    __syncthreads();
    // Hillis-Steele inclusive scan
    for (int off = 1; off < 1024; off <<= 1) {
        int v = (t >= off) ? part[t - off] : 0;
        __syncthreads();
        part[t] += v;
        __syncthreads();
    }
    int run = (t > 0) ? part[t - 1] : 0;
    for (int i = b0; i < b1; i++) { g_off[i] = run; run += g_deg[i] - 1; }
}

// ---------------- graph start offsets (batch sorted; tiny scan) ---------------
__global__ void goff_kernel() {
    if (threadIdx.x == 0) {
        int run = 0;
        for (int g = 0; g < N_GRAPHS_; g++) { g_goff[g] = run; run += g_cnt[g]; }
    }
}

// ---------------- CSR fill -----------------------------------------------------
__global__ void fill_kernel(const void* __restrict__ ei) {
    int e = blockIdx.x * blockDim.x + threadIdx.x;
    if (e >= N_EDGES_) return;
    int s = load_idx(ei, e);
    int d = load_idx(ei, N_EDGES_ + e);
    if (s < 0 || s >= N_NODES_ || d < 0 || d >= N_NODES_) return;
    int pos = g_off[d] + atomicAdd(&g_cur[d], 1);
    g_csrc[pos]  = s;
    g_cnorm[pos] = g_dis[s] * g_dis[d];
}

// ---------------- 128x128x8 tiled SGEMM -> g_h --------------------------------
// FIRST=true : A = external x with fused standardization
// FIRST=false: A = g_y (device global, referenced in device code)
template <bool FIRST>
__global__ __launch_bounds__(256)
void sgemm(const float* __restrict__ Aext, const float* __restrict__ W) {
    const float* __restrict__ A = FIRST ? Aext : (const float*)g_y;
    float* __restrict__ C = g_h;

    __shared__ float As[8][128];
    __shared__ float Bs[8][128];
    const int M = N_NODES_;
    int bm = blockIdx.y * 128;
    int bn = blockIdx.x * 128;
    int tid = threadIdx.x;
    int trow = tid >> 4;          // 0..15
    int tcol = tid & 15;          // 0..15

    int a_row = tid >> 1;         // 0..127
    int a_col = (tid & 1) * 4;    // 0 or 4
    int b_row = tid >> 5;         // 0..7
    int b_col = (tid & 31) * 4;   // 0..124

    float acc[8][8];
    #pragma unroll
    for (int i = 0; i < 8; i++)
        #pragma unroll
        for (int j = 0; j < 8; j++) acc[i][j] = 0.f;

    for (int k0 = 0; k0 < DIM; k0 += 8) {
        float4 av = make_float4(0.f, 0.f, 0.f, 0.f);
        int gm = bm + a_row;
        if (gm < M) av = *(const float4*)(A + (size_t)gm * DIM + k0 + a_col);
        if (FIRST) {
            int kc = k0 + a_col;
            av.x = (av.x - g_mu[kc + 0]) * g_isd[kc + 0];
            av.y = (av.y - g_mu[kc + 1]) * g_isd[kc + 1];
            av.z = (av.z - g_mu[kc + 2]) * g_isd[kc + 2];
            av.w = (av.w - g_mu[kc + 3]) * g_isd[kc + 3];
        }
        As[a_col + 0][a_row] = av.x;
        As[a_col + 1][a_row] = av.y;
        As[a_col + 2][a_row] = av.z;
        As[a_col + 3][a_row] = av.w;

        float4 bv = *(const float4*)(W + (size_t)(k0 + b_row) * DIM + bn + b_col);
        *(float4*)&Bs[b_row][b_col] = bv;
        __syncthreads();

        #pragma unroll
        for (int kk = 0; kk < 8; kk++) {
            float4 a0 = *(float4*)&As[kk][trow * 8];
            float4 a1 = *(float4*)&As[kk][trow * 8 + 4];
            float4 b0 = *(float4*)&Bs[kk][tcol * 8];
            float4 b1 = *(float4*)&Bs[kk][tcol * 8 + 4];
            float a[8] = {a0.x, a0.y, a0.z, a0.w, a1.x, a1.y, a1.z, a1.w};
            float b[8] = {b0.x, b0.y, b0.z, b0.w, b1.x, b1.y, b1.z, b1.w};
            #pragma unroll
            for (int i = 0; i < 8; i++)
                #pragma unroll
                for (int j = 0; j < 8; j++) acc[i][j] += a[i] * b[j];
        }
        __syncthreads();
    }

    #pragma unroll
    for (int i = 0; i < 8; i++) {
        int gm = bm + trow * 8 + i;
        if (gm >= M) continue;
        float* cp = C + (size_t)gm * DIM + bn + tcol * 8;
        *(float4*)(cp + 0) = make_float4(acc[i][0], acc[i][1], acc[i][2], acc[i][3]);
        *(float4*)(cp + 4) = make_float4(acc[i][4], acc[i][5], acc[i][6], acc[i][7]);
    }
}

// ---------------- fused gather conv: g_y = propagate(g_h) + b (opt ReLU) ------
// one warp per node; no atomics.
template <bool RELU>
__global__ __launch_bounds__(256)
void gather_kernel(const float* __restrict__ b) {
    const float* __restrict__ h = (const float*)g_h;
    float* __restrict__ y = (float*)g_y;

    int node = blockIdx.x * 8 + (threadIdx.x >> 5);
    int lane = threadIdx.x & 31;
    if (node >= N_NODES_) return;

    float dn = g_dis[node];
    float self_w = dn * dn;
    const float4* hn = (const float4*)(h + (size_t)node * DIM);

    float4 acc[4];
    #pragma unroll
    for (int c = 0; c < 4; c++) {
        float4 v = hn[lane + 32 * c];
        acc[c] = make_float4(v.x * self_w, v.y * self_w, v.z * self_w, v.w * self_w);
    }

    int beg = g_off[node];
    int end = beg + g_deg[node] - 1;
    for (int e = beg; e < end; e++) {
        int s   = g_csrc[e];
        float w = g_cnorm[e];
        const float4* hs = (const float4*)(h + (size_t)s * DIM);
        #pragma unroll
        for (int c = 0; c < 4; c++) {
            float4 v = hs[lane + 32 * c];
            acc[c].x = fmaf(v.x, w, acc[c].x);
            acc[c].y = fmaf(v.y, w, acc[c].y);
            acc[c].z = fmaf(v.z, w, acc[c].z);
            acc[c].w = fmaf(v.w, w, acc[c].w);
        }
    }

    float4* yn = (float4*)(y + (size_t)node * DIM);
    const float4* bb = (const float4*)b;
    #pragma unroll
    for (int c = 0; c < 4; c++) {
        float4 bv = bb[lane + 32 * c];
        float4 r;
        r.x = acc[c].x + bv.x; r.y = acc[c].y + bv.y;
        r.z = acc[c].z + bv.z; r.w = acc[c].w + bv.w;
        if (RELU) {
            r.x = fmaxf(r.x, 0.f); r.y = fmaxf(r.y, 0.f);
            r.z = fmaxf(r.z, 0.f); r.w = fmaxf(r.w, 0.f);
        }
        yn[lane + 32 * c] = r;
    }
}

// ---------------- global mean pool via sorted-batch segments -----------------
__global__ __launch_bounds__(512)
void pool_kernel() {
    int g = blockIdx.x;
    int j = threadIdx.x;
    int beg = g_goff[g];
    int cnt = g_cnt[g];
    float s = 0.f;
    for (int r = beg; r < beg + cnt; r++)
        s += g_y[(size_t)r * DIM + j];
    g_pool[(size_t)g * DIM + j] = s / fmaxf((float)cnt, 1.f);
}

// ---------------- final: out[g] = pool[g] @ Wlin + blin ----------------------
__global__ __launch_bounds__(512)
void final_gemm(const float* __restrict__ Wlin, const float* __restrict__ blin,
                float* __restrict__ out) {
    int g = blockIdx.x;
    int j = threadIdx.x;
    __shared__ float sp[DIM];
    sp[j] = g_pool[(size_t)g * DIM + j];
    __syncthreads();
    float acc = blin[j];
    #pragma unroll 8
    for (int k = 0; k < DIM; k++)
        acc = fmaf(sp[k], __ldg(&Wlin[(size_t)k * DIM + j]), acc);
    out[(size_t)g * DIM + j] = acc;
}

// ---------------- launcher ---------------------------------------------------
extern "C" void kernel_launch(void* const* d_in, const int* in_sizes, int n_in,
                              void* d_out, int out_size) {
    const float* x    = (const float*)d_in[0];
    const void*  ei   = d_in[1];            // [2, E], int32 or int64
    const void*  batch= d_in[2];            // [N], int32 or int64
    const float* W1   = (const float*)d_in[3];
    const float* b1   = (const float*)d_in[4];
    const float* W2   = (const float*)d_in[5];
    const float* b2   = (const float*)d_in[6];
    const float* Wlin = (const float*)d_in[7];
    const float* blin = (const float*)d_in[8];
    float* out = (float*)d_out;

    // dtype detect + init + stats + graph structure
    detect_kernel<<<1, 32>>>((const int*)ei);
    init_kernel<<<(N_NODES_ + 255) / 256, 256>>>();
    col_stats<<<(N_NODES_ + ROWS_PER_BLOCK - 1) / ROWS_PER_BLOCK, 256>>>(x);
    finalize_stats<<<2, 256>>>();
    degree_kernel<<<(N_EDGES_ + 255) / 256, 256>>>(ei, batch);
    dis_kernel<<<(N_NODES_ + 255) / 256, 256>>>();
    scan_kernel<<<1, 1024>>>();
    goff_kernel<<<1, 32>>>();
    fill_kernel<<<(N_EDGES_ + 255) / 256, 256>>>(ei);

    dim3 gblock(256);
    dim3 ggrid(DIM / 128, (N_NODES_ + 127) / 128);

    // ---- conv1: g_h = standardize(x) @ W1 ; g_y = relu(propagate(g_h) + b1)
    sgemm<true><<<ggrid, gblock>>>(x, W1);
    gather_kernel<true><<<(N_NODES_ + 7) / 8, 256>>>(b1);

    // ---- conv2: g_h = g_y @ W2 ; g_y = propagate(g_h) + b2
    sgemm<false><<<ggrid, gblock>>>(nullptr, W2);
    gather_kernel<false><<<(N_NODES_ + 7) / 8, 256>>>(b2);

    // ---- pool + final linear
    pool_kernel<<<N_GRAPHS_, 512>>>();
    final_gemm<<<N_GRAPHS_, 512>>>(Wlin, blin, out);
}

// round 5
// speedup vs baseline: 1.0485x; 1.0485x over previous
#include <cuda_runtime.h>
#include <cuda_bf16.h>
#include <math.h>

#define N_NODES_ 20000
#define N_EDGES_ 160000
#define DIM 512
#define N_GRAPHS_ 128

// ---------------- scratch (device globals; referenced ONLY in device code) ---
__device__ float g_h[N_NODES_ * DIM];     // GEMM output / message source
__device__ float g_y[N_NODES_ * DIM];     // conv output / activations
__device__ float g_colsum[DIM];
__device__ float g_colsq[DIM];
__device__ float g_mu[DIM];
__device__ float g_isd[DIM];
__device__ int   g_deg[N_NODES_];         // 1 (self) + in-degree
__device__ float g_dis[N_NODES_];         // deg^{-1/2}
__device__ int   g_off[N_NODES_];         // CSR offsets (in-edges, excl. self)
__device__ int   g_cur[N_NODES_];         // fill cursors
__device__ int   g_csrc[N_EDGES_];        // CSR: source node per in-edge
__device__ float g_cnorm[N_EDGES_];       // CSR: dis[src]*dis[dst]
__device__ float g_pool[N_GRAPHS_ * DIM]; // pooled means
__device__ int   g_cnt[N_GRAPHS_];
__device__ int   g_goff[N_GRAPHS_];       // graph start row (batch is sorted)
__device__ int   g_is64;                  // 1 if index inputs are int64

// packed fp32x2 FMA (Blackwell FFMA2) -----------------------------------------
#define FMA_F32X2(d, a, b) \
    asm("fma.rn.f32x2 %0, %1, %2, %0;" : "+l"(d) : "l"(a), "l"(b))

__device__ __forceinline__ unsigned long long pack_dup(float v) {
    unsigned long long r;
    unsigned int u = __float_as_uint(v);
    asm("mov.b64 %0, {%1,%2};" : "=l"(r) : "r"(u), "r"(u));
    return r;
}

// ---------------- dtype detection (int64 vs int32 indices) -------------------
__global__ void detect_kernel(const int* __restrict__ ei32) {
    if (threadIdx.x == 0 && blockIdx.x == 0) {
        int all_hi_zero = 1;
        #pragma unroll
        for (int i = 0; i < 16; i++) all_hi_zero &= (ei32[2 * i + 1] == 0);
        g_is64 = all_hi_zero;
    }
}

__device__ __forceinline__ int load_idx(const void* p, int e) {
    if (g_is64) return (int)((const long long*)p)[e];
    return ((const int*)p)[e];
}

// ---------------- init --------------------------------------------------------
__global__ void init_kernel() {
    int i = blockIdx.x * blockDim.x + threadIdx.x;
    if (i < N_NODES_) { g_deg[i] = 1; g_cur[i] = 0; }
    if (i < DIM)      { g_colsum[i] = 0.f; g_colsq[i] = 0.f; }
    if (i < N_GRAPHS_)  g_cnt[i] = 0;
}

// ---------------- column mean / std (population) -----------------------------
#define ROWS_PER_BLOCK 100
__global__ void col_stats(const float* __restrict__ x) {
    int t = threadIdx.x;               // 256 threads
    int c0 = t, c1 = t + 256;
    float s0 = 0.f, s1 = 0.f, q0 = 0.f, q1 = 0.f;
    int r0 = blockIdx.x * ROWS_PER_BLOCK;
    int r1 = min(r0 + ROWS_PER_BLOCK, N_NODES_);
    for (int r = r0; r < r1; r++) {
        float v0 = x[(size_t)r * DIM + c0];
        float v1 = x[(size_t)r * DIM + c1];
        s0 += v0; q0 += v0 * v0;
        s1 += v1; q1 += v1 * v1;
    }
    atomicAdd(&g_colsum[c0], s0); atomicAdd(&g_colsq[c0], q0);
    atomicAdd(&g_colsum[c1], s1); atomicAdd(&g_colsq[c1], q1);
}

__global__ void finalize_stats() {
    int j = blockIdx.x * blockDim.x + threadIdx.x;
    if (j >= DIM) return;
    float mean = g_colsum[j] * (1.f / (float)N_NODES_);
    float var  = g_colsq[j] * (1.f / (float)N_NODES_) - mean * mean;
    float sd   = sqrtf(fmaxf(var, 0.f));
    g_mu[j]  = mean;
    g_isd[j] = (sd > 0.f) ? (1.f / sd) : 1.f;
}

// ---------------- degree / normalization / batch histogram -------------------
__global__ void degree_kernel(const void* __restrict__ ei,
                              const void* __restrict__ batch) {
    int e = blockIdx.x * blockDim.x + threadIdx.x;
    if (e < N_EDGES_) {
        int d = load_idx(ei, N_EDGES_ + e);
        if (d >= 0 && d < N_NODES_) atomicAdd(&g_deg[d], 1);
    }
    if (e < N_NODES_) {
        int g = load_idx(batch, e);
        if (g >= 0 && g < N_GRAPHS_) atomicAdd(&g_cnt[g], 1);
    }
}

__global__ void dis_kernel() {
    int i = blockIdx.x * blockDim.x + threadIdx.x;
    if (i < N_NODES_) g_dis[i] = rsqrtf((float)g_deg[i]);
}

// ---------------- exclusive prefix scan over in-edge counts (1 block) --------
__global__ __launch_bounds__(1024)
void scan_kernel() {
    __shared__ int part[1024];
    int t = threadIdx.x;
    const int CH = (N_NODES_ + 1023) / 1024;   // 20
    int b0 = t * CH, b1 = min(b0 + CH, N_NODES_);
    int s = 0;
    for (int i = b0; i < b1; i++) s += g_deg[i] - 1;
    part[t] = s;
    __syncthreads();
    for (int off = 1; off < 1024; off <<= 1) {
        int v = (t >= off) ? part[t - off] : 0;
        __syncthreads();
        part[t] += v;
        __syncthreads();
    }
    int run = (t > 0) ? part[t - 1] : 0;
    for (int i = b0; i < b1; i++) { g_off[i] = run; run += g_deg[i] - 1; }
}

// ---------------- graph start offsets (batch sorted; tiny scan) ---------------
__global__ void goff_kernel() {
    if (threadIdx.x == 0) {
        int run = 0;
        for (int g = 0; g < N_GRAPHS_; g++) { g_goff[g] = run; run += g_cnt[g]; }
    }
}

// ---------------- CSR fill -----------------------------------------------------
__global__ void fill_kernel(const void* __restrict__ ei) {
    int e = blockIdx.x * blockDim.x + threadIdx.x;
    if (e >= N_EDGES_) return;
    int s = load_idx(ei, e);
    int d = load_idx(ei, N_EDGES_ + e);
    if (s < 0 || s >= N_NODES_ || d < 0 || d >= N_NODES_) return;
    int pos = g_off[d] + atomicAdd(&g_cur[d], 1);
    g_csrc[pos]  = s;
    g_cnorm[pos] = g_dis[s] * g_dis[d];
}

// ---------------- 128x128x8 tiled SGEMM (FFMA2 + double buffer) -> g_h --------
// FIRST=true : A = external x with fused standardization
// FIRST=false: A = g_y
template <bool FIRST>
__global__ __launch_bounds__(256, 2)
void sgemm(const float* __restrict__ Aext, const float* __restrict__ W) {
    const float* __restrict__ A = FIRST ? Aext : (const float*)g_y;
    float* __restrict__ C = g_h;

    __shared__ float As[2][8][128];
    __shared__ float Bs[2][8][128];
    const int M = N_NODES_;
    int bm = blockIdx.y * 128;
    int bn = blockIdx.x * 128;
    int tid = threadIdx.x;
    int trow = tid >> 4;          // 0..15
    int tcol = tid & 15;          // 0..15

    int a_row = tid >> 1;         // 0..127
    int a_col = (tid & 1) * 4;    // 0 or 4
    int b_row = tid >> 5;         // 0..7
    int b_col = (tid & 31) * 4;   // 0..124

    // acc2[i][j2]: packed pair (col 2*j2, 2*j2+1) for row i
    unsigned long long acc2[8][4];
    #pragma unroll
    for (int i = 0; i < 8; i++)
        #pragma unroll
        for (int j = 0; j < 4; j++) acc2[i][j] = 0ull;

    int gm_a = bm + a_row;

    // ---- prologue: load k0=0 tile into buffer 0
    {
        float4 av = make_float4(0.f, 0.f, 0.f, 0.f);
        if (gm_a < M) av = *(const float4*)(A + (size_t)gm_a * DIM + a_col);
        if (FIRST) {
            av.x = (av.x - g_mu[a_col + 0]) * g_isd[a_col + 0];
            av.y = (av.y - g_mu[a_col + 1]) * g_isd[a_col + 1];
            av.z = (av.z - g_mu[a_col + 2]) * g_isd[a_col + 2];
            av.w = (av.w - g_mu[a_col + 3]) * g_isd[a_col + 3];
        }
        As[0][a_col + 0][a_row] = av.x;
        As[0][a_col + 1][a_row] = av.y;
        As[0][a_col + 2][a_row] = av.z;
        As[0][a_col + 3][a_row] = av.w;
        float4 bv = *(const float4*)(W + (size_t)b_row * DIM + bn + b_col);
        *(float4*)&Bs[0][b_row][b_col] = bv;
    }
    __syncthreads();

    int buf = 0;
    for (int k0 = 0; k0 < DIM; k0 += 8) {
        // prefetch next K-slab into registers (latency overlapped with compute)
        float4 av_n, bv_n;
        bool more = (k0 + 8) < DIM;
        if (more) {
            av_n = make_float4(0.f, 0.f, 0.f, 0.f);
            if (gm_a < M) av_n = *(const float4*)(A + (size_t)gm_a * DIM + k0 + 8 + a_col);
            if (FIRST) {
                int kc = k0 + 8 + a_col;
                av_n.x = (av_n.x - g_mu[kc + 0]) * g_isd[kc + 0];
                av_n.y = (av_n.y - g_mu[kc + 1]) * g_isd[kc + 1];
                av_n.z = (av_n.z - g_mu[kc + 2]) * g_isd[kc + 2];
                av_n.w = (av_n.w - g_mu[kc + 3]) * g_isd[kc + 3];
            }
            bv_n = *(const float4*)(W + (size_t)(k0 + 8 + b_row) * DIM + bn + b_col);
        }

        #pragma unroll
        for (int kk = 0; kk < 8; kk++) {
            float4 a0 = *(float4*)&As[buf][kk][trow * 8];
            float4 a1 = *(float4*)&As[buf][kk][trow * 8 + 4];
            // b as packed 64-bit pairs (8 floats = 4 pairs)
            ulonglong2 bp0 = *(ulonglong2*)&Bs[buf][kk][tcol * 8];
            ulonglong2 bp1 = *(ulonglong2*)&Bs[buf][kk][tcol * 8 + 4];
            unsigned long long bb[4] = {bp0.x, bp0.y, bp1.x, bp1.y};
            float a[8] = {a0.x, a0.y, a0.z, a0.w, a1.x, a1.y, a1.z, a1.w};
            #pragma unroll
            for (int i = 0; i < 8; i++) {
                unsigned long long aa = pack_dup(a[i]);
                #pragma unroll
                for (int j = 0; j < 4; j++)
                    FMA_F32X2(acc2[i][j], aa, bb[j]);
            }
        }

        if (more) {
            int nb = buf ^ 1;
            As[nb][a_col + 0][a_row] = av_n.x;
            As[nb][a_col + 1][a_row] = av_n.y;
            As[nb][a_col + 2][a_row] = av_n.z;
            As[nb][a_col + 3][a_row] = av_n.w;
            *(float4*)&Bs[nb][b_row][b_col] = bv_n;
        }
        __syncthreads();
        buf ^= 1;
    }

    #pragma unroll
    for (int i = 0; i < 8; i++) {
        int gm = bm + trow * 8 + i;
        if (gm >= M) continue;
        float* cp = C + (size_t)gm * DIM + bn + tcol * 8;
        // acc2[i][0..3] is exactly 8 contiguous fp32 (cols j..j+7)
        *(float4*)(cp + 0) = *(float4*)&acc2[i][0];
        *(float4*)(cp + 4) = *(float4*)&acc2[i][2];
    }
}

// ---------------- fused gather conv: g_y = propagate(g_h) + b (opt ReLU) ------
template <bool RELU>
__global__ __launch_bounds__(256)
void gather_kernel(const float* __restrict__ b) {
    const float* __restrict__ h = (const float*)g_h;
    float* __restrict__ y = (float*)g_y;

    int node = blockIdx.x * 8 + (threadIdx.x >> 5);
    int lane = threadIdx.x & 31;
    if (node >= N_NODES_) return;

    float dn = g_dis[node];
    float self_w = dn * dn;
    const float4* hn = (const float4*)(h + (size_t)node * DIM);

    float4 acc[4];
    #pragma unroll
    for (int c = 0; c < 4; c++) {
        float4 v = hn[lane + 32 * c];
        acc[c] = make_float4(v.x * self_w, v.y * self_w, v.z * self_w, v.w * self_w);
    }

    int beg = g_off[node];
    int end = beg + g_deg[node] - 1;
    for (int e = beg; e < end; e++) {
        int s   = g_csrc[e];
        float w = g_cnorm[e];
        const float4* hs = (const float4*)(h + (size_t)s * DIM);
        #pragma unroll
        for (int c = 0; c < 4; c++) {
            float4 v = hs[lane + 32 * c];
            acc[c].x = fmaf(v.x, w, acc[c].x);
            acc[c].y = fmaf(v.y, w, acc[c].y);
            acc[c].z = fmaf(v.z, w, acc[c].z);
            acc[c].w = fmaf(v.w, w, acc[c].w);
        }
    }

    float4* yn = (float4*)(y + (size_t)node * DIM);
    const float4* bb = (const float4*)b;
    #pragma unroll
    for (int c = 0; c < 4; c++) {
        float4 bv = bb[lane + 32 * c];
        float4 r;
        r.x = acc[c].x + bv.x; r.y = acc[c].y + bv.y;
        r.z = acc[c].z + bv.z; r.w = acc[c].w + bv.w;
        if (RELU) {
            r.x = fmaxf(r.x, 0.f); r.y = fmaxf(r.y, 0.f);
            r.z = fmaxf(r.z, 0.f); r.w = fmaxf(r.w, 0.f);
        }
        yn[lane + 32 * c] = r;
    }
}

// ---------------- global mean pool via sorted-batch segments -----------------
__global__ __launch_bounds__(512)
void pool_kernel() {
    int g = blockIdx.x;
    int j = threadIdx.x;
    int beg = g_goff[g];
    int cnt = g_cnt[g];
    float s = 0.f;
    for (int r = beg; r < beg + cnt; r++)
        s += g_y[(size_t)r * DIM + j];
    g_pool[(size_t)g * DIM + j] = s / fmaxf((float)cnt, 1.f);
}

// ---------------- final: out[g] = pool[g] @ Wlin + blin ----------------------
__global__ __launch_bounds__(512)
void final_gemm(const float* __restrict__ Wlin, const float* __restrict__ blin,
                float* __restrict__ out) {
    int g = blockIdx.x;
    int j = threadIdx.x;
    __shared__ float sp[DIM];
    sp[j] = g_pool[(size_t)g * DIM + j];
    __syncthreads();
    float acc = blin[j];
    #pragma unroll 8
    for (int k = 0; k < DIM; k++)
        acc = fmaf(sp[k], __ldg(&Wlin[(size_t)k * DIM + j]), acc);
    out[(size_t)g * DIM + j] = acc;
}

// ---------------- launcher ---------------------------------------------------
extern "C" void kernel_launch(void* const* d_in, const int* in_sizes, int n_in,
                              void* d_out, int out_size) {
    const float* x    = (const float*)d_in[0];
    const void*  ei   = d_in[1];            // [2, E], int32 or int64
    const void*  batch= d_in[2];            // [N], int32 or int64
    const float* W1   = (const float*)d_in[3];
    const float* b1   = (const float*)d_in[4];
    const float* W2   = (const float*)d_in[5];
    const float* b2   = (const float*)d_in[6];
    const float* Wlin = (const float*)d_in[7];
    const float* blin = (const float*)d_in[8];
    float* out = (float*)d_out;

    detect_kernel<<<1, 32>>>((const int*)ei);
    init_kernel<<<(N_NODES_ + 255) / 256, 256>>>();
    col_stats<<<(N_NODES_ + ROWS_PER_BLOCK - 1) / ROWS_PER_BLOCK, 256>>>(x);
    finalize_stats<<<2, 256>>>();
    degree_kernel<<<(N_EDGES_ + 255) / 256, 256>>>(ei, batch);
    dis_kernel<<<(N_NODES_ + 255) / 256, 256>>>();
    scan_kernel<<<1, 1024>>>();
    goff_kernel<<<1, 32>>>();
    fill_kernel<<<(N_EDGES_ + 255) / 256, 256>>>(ei);

    dim3 gblock(256);
    dim3 ggrid(DIM / 128, (N_NODES_ + 127) / 128);

    // ---- conv1
    sgemm<true><<<ggrid, gblock>>>(x, W1);
    gather_kernel<true><<<(N_NODES_ + 7) / 8, 256>>>(b1);

    // ---- conv2
    sgemm<false><<<ggrid, gblock>>>(nullptr, W2);
    gather_kernel<false><<<(N_NODES_ + 7) / 8, 256>>>(b2);

    // ---- pool + final linear
    pool_kernel<<<N_GRAPHS_, 512>>>();
    final_gemm<<<N_GRAPHS_, 512>>>(Wlin, blin, out);
}

// round 7
// speedup vs baseline: 1.9565x; 1.8660x over previous
#include <cuda_runtime.h>
#include <cuda_bf16.h>
#include <math.h>

#define N_NODES_ 20000
#define N_EDGES_ 160000
#define DIM 512
#define N_GRAPHS_ 128

// ---------------- scratch (device globals; referenced ONLY in device code) ---
__device__ float g_h[N_NODES_ * DIM];     // GEMM output / message source
__device__ float g_y[N_NODES_ * DIM];     // conv output / activations
__device__ float g_colsum[DIM];
__device__ float g_colsq[DIM];
__device__ float g_mu[DIM];
__device__ float g_isd[DIM];
__device__ int   g_deg[N_NODES_];
__device__ float g_dis[N_NODES_];
__device__ int   g_off[N_NODES_];
__device__ int   g_cur[N_NODES_];
__device__ int   g_csrc[N_EDGES_];
__device__ float g_cnorm[N_EDGES_];
__device__ float g_pool[N_GRAPHS_ * DIM];
__device__ int   g_cnt[N_GRAPHS_];
__device__ int   g_goff[N_GRAPHS_];
__device__ int   g_is64;

// bf16 split operands for tensor-core GEMM
__device__ __nv_bfloat16 g_ahi[N_NODES_ * DIM];
__device__ __nv_bfloat16 g_alo[N_NODES_ * DIM];
__device__ __nv_bfloat16 g_w1h[DIM * DIM];   // transposed: [n][k]
__device__ __nv_bfloat16 g_w1l[DIM * DIM];
__device__ __nv_bfloat16 g_w2h[DIM * DIM];
__device__ __nv_bfloat16 g_w2l[DIM * DIM];

// ---------------- helpers ------------------------------------------------------
__device__ __forceinline__ unsigned smem_u32(const void* p) {
    unsigned r;
    asm("{ .reg .u64 t; cvta.to.shared.u64 t, %1; cvt.u32.u64 %0, t; }"
        : "=r"(r) : "l"(p));
    return r;
}

__device__ __forceinline__ void ldsm_x4(unsigned* r, unsigned addr) {
    asm volatile("ldmatrix.sync.aligned.m8n8.x4.shared.b16 {%0,%1,%2,%3}, [%4];"
                 : "=r"(r[0]), "=r"(r[1]), "=r"(r[2]), "=r"(r[3]) : "r"(addr));
}

__device__ __forceinline__ void mma16816(float* c, const unsigned* a, const unsigned* b) {
    asm volatile(
        "mma.sync.aligned.m16n8k16.row.col.f32.bf16.bf16.f32 "
        "{%0,%1,%2,%3}, {%4,%5,%6,%7}, {%8,%9}, {%0,%1,%2,%3};"
        : "+f"(c[0]), "+f"(c[1]), "+f"(c[2]), "+f"(c[3])
        : "r"(a[0]), "r"(a[1]), "r"(a[2]), "r"(a[3]), "r"(b[0]), "r"(b[1]));
}

__device__ __forceinline__ void cp16(unsigned dst, const void* src, int sz) {
    asm volatile("cp.async.cg.shared.global [%0], [%1], 16, %2;"
                 :: "r"(dst), "l"(src), "r"(sz) : "memory");
}

// ---------------- dtype detection (int64 vs int32 indices) -------------------
__global__ void detect_kernel(const int* __restrict__ ei32) {
    if (threadIdx.x == 0 && blockIdx.x == 0) {
        int all_hi_zero = 1;
        #pragma unroll
        for (int i = 0; i < 16; i++) all_hi_zero &= (ei32[2 * i + 1] == 0);
        g_is64 = all_hi_zero;
    }
}

__device__ __forceinline__ int load_idx(const void* p, int e) {
    if (g_is64) return (int)((const long long*)p)[e];
    return ((const int*)p)[e];
}

// ---------------- init --------------------------------------------------------
__global__ void init_kernel() {
    int i = blockIdx.x * blockDim.x + threadIdx.x;
    if (i < N_NODES_) { g_deg[i] = 1; g_cur[i] = 0; }
    if (i < DIM)      { g_colsum[i] = 0.f; g_colsq[i] = 0.f; }
    if (i < N_GRAPHS_)  g_cnt[i] = 0;
}

// ---------------- column mean / std (population) -----------------------------
#define ROWS_PER_BLOCK 100
__global__ void col_stats(const float* __restrict__ x) {
    int t = threadIdx.x;
    int c0 = t, c1 = t + 256;
    float s0 = 0.f, s1 = 0.f, q0 = 0.f, q1 = 0.f;
    int r0 = blockIdx.x * ROWS_PER_BLOCK;
    int r1 = min(r0 + ROWS_PER_BLOCK, N_NODES_);
    for (int r = r0; r < r1; r++) {
        float v0 = x[(size_t)r * DIM + c0];
        float v1 = x[(size_t)r * DIM + c1];
        s0 += v0; q0 += v0 * v0;
        s1 += v1; q1 += v1 * v1;
    }
    atomicAdd(&g_colsum[c0], s0); atomicAdd(&g_colsq[c0], q0);
    atomicAdd(&g_colsum[c1], s1); atomicAdd(&g_colsq[c1], q1);
}

__global__ void finalize_stats() {
    int j = blockIdx.x * blockDim.x + threadIdx.x;
    if (j >= DIM) return;
    float mean = g_colsum[j] * (1.f / (float)N_NODES_);
    float var  = g_colsq[j] * (1.f / (float)N_NODES_) - mean * mean;
    float sd   = sqrtf(fmaxf(var, 0.f));
    g_mu[j]  = mean;
    g_isd[j] = (sd > 0.f) ? (1.f / sd) : 1.f;
}

// ---------------- degree / batch histogram -----------------------------------
__global__ void degree_kernel(const void* __restrict__ ei,
                              const void* __restrict__ batch) {
    int e = blockIdx.x * blockDim.x + threadIdx.x;
    if (e < N_EDGES_) {
        int d = load_idx(ei, N_EDGES_ + e);
        if (d >= 0 && d < N_NODES_) atomicAdd(&g_deg[d], 1);
    }
    if (e < N_NODES_) {
        int g = load_idx(batch, e);
        if (g >= 0 && g < N_GRAPHS_) atomicAdd(&g_cnt[g], 1);
    }
}

__global__ void dis_kernel() {
    int i = blockIdx.x * blockDim.x + threadIdx.x;
    if (i < N_NODES_) g_dis[i] = rsqrtf((float)g_deg[i]);
}

// ---------------- prefix scan over in-edge counts (1 block) -------------------
__global__ __launch_bounds__(1024)
void scan_kernel() {
    __shared__ int part[1024];
    int t = threadIdx.x;
    const int CH = (N_NODES_ + 1023) / 1024;
    int b0 = t * CH, b1 = min(b0 + CH, N_NODES_);
    int s = 0;
    for (int i = b0; i < b1; i++) s += g_deg[i] - 1;
    part[t] = s;
    __syncthreads();
    for (int off = 1; off < 1024; off <<= 1) {
        int v = (t >= off) ? part[t - off] : 0;
        __syncthreads();
        part[t] += v;
        __syncthreads();
    }
    int run = (t > 0) ? part[t - 1] : 0;
    for (int i = b0; i < b1; i++) { g_off[i] = run; run += g_deg[i] - 1; }
}

__global__ void goff_kernel() {
    if (threadIdx.x == 0) {
        int run = 0;
        for (int g = 0; g < N_GRAPHS_; g++) { g_goff[g] = run; run += g_cnt[g]; }
    }
}

// ---------------- CSR fill -----------------------------------------------------
__global__ void fill_kernel(const void* __restrict__ ei) {
    int e = blockIdx.x * blockDim.x + threadIdx.x;
    if (e >= N_EDGES_) return;
    int s = load_idx(ei, e);
    int d = load_idx(ei, N_EDGES_ + e);
    if (s < 0 || s >= N_NODES_ || d < 0 || d >= N_NODES_) return;
    int pos = g_off[d] + atomicAdd(&g_cur[d], 1);
    g_csrc[pos]  = s;
    g_cnorm[pos] = g_dis[s] * g_dis[d];
}

// ---------------- weight transpose + bf16 hi/lo split --------------------------
__global__ void convW(const float* __restrict__ W1, const float* __restrict__ W2) {
    int t = blockIdx.x * blockDim.x + threadIdx.x;   // 2*512*512
    int sel = t >> 18;
    int r = t & 262143;
    int n = r >> 9;
    int k = r & 511;
    float v = (sel ? W2 : W1)[(size_t)k * DIM + n];
    __nv_bfloat16 hi = __float2bfloat16_rn(v);
    __nv_bfloat16 lo = __float2bfloat16_rn(v - __bfloat162float(hi));
    if (sel) { g_w2h[(size_t)n * DIM + k] = hi; g_w2l[(size_t)n * DIM + k] = lo; }
    else     { g_w1h[(size_t)n * DIM + k] = hi; g_w1l[(size_t)n * DIM + k] = lo; }
}

// ---------------- activation bf16 hi/lo split (opt fused standardization) -----
template <bool FIRST>
__global__ void convA(const float* __restrict__ src) {
    int i = blockIdx.x * blockDim.x + threadIdx.x;   // float4 index
    if (i >= N_NODES_ * DIM / 4) return;
    const float* s = FIRST ? src : (const float*)g_y;
    float4 v = ((const float4*)s)[i];
    if (FIRST) {
        int c = (i << 2) & (DIM - 1);
        v.x = (v.x - g_mu[c + 0]) * g_isd[c + 0];
        v.y = (v.y - g_mu[c + 1]) * g_isd[c + 1];
        v.z = (v.z - g_mu[c + 2]) * g_isd[c + 2];
        v.w = (v.w - g_mu[c + 3]) * g_isd[c + 3];
    }
    __nv_bfloat16 h0 = __float2bfloat16_rn(v.x);
    __nv_bfloat16 h1 = __float2bfloat16_rn(v.y);
    __nv_bfloat16 h2 = __float2bfloat16_rn(v.z);
    __nv_bfloat16 h3 = __float2bfloat16_rn(v.w);
    __nv_bfloat16 l0 = __float2bfloat16_rn(v.x - __bfloat162float(h0));
    __nv_bfloat16 l1 = __float2bfloat16_rn(v.y - __bfloat162float(h1));
    __nv_bfloat16 l2 = __float2bfloat16_rn(v.z - __bfloat162float(h2));
    __nv_bfloat16 l3 = __float2bfloat16_rn(v.w - __bfloat162float(h3));
    uint2 uh, ul;
    uh.x = ((unsigned)__bfloat16_as_ushort(h1) << 16) | __bfloat16_as_ushort(h0);
    uh.y = ((unsigned)__bfloat16_as_ushort(h3) << 16) | __bfloat16_as_ushort(h2);
    ul.x = ((unsigned)__bfloat16_as_ushort(l1) << 16) | __bfloat16_as_ushort(l0);
    ul.y = ((unsigned)__bfloat16_as_ushort(l3) << 16) | __bfloat16_as_ushort(l2);
    ((uint2*)g_ahi)[i] = uh;
    ((uint2*)g_alo)[i] = ul;
}

// ---------------- HMMA GEMM: g_h[M,512] = A(split) @ W(split)^T ----------------
// mma.sync m16n8k16 bf16, 3-split fp32 emulation. BM=BN=128, BK=32, 4 warps
// (2x2), warp tile 64x64, cp.async double buffer. SMEM rows padded to 80B.
#define STG   10240            // one stage of one array: 128 rows * 80B
#define OFF_AH 0
#define OFF_AL 20480
#define OFF_BH 40960
#define OFF_BL 61440
#define SMEM_HMMA 81920
#define NK 16                  // 512 / 32

template <int WSEL>
__global__ __launch_bounds__(128)
void hmma_gemm() {
    extern __shared__ char smem[];
    const __nv_bfloat16* bth = (WSEL == 1) ? (const __nv_bfloat16*)g_w1h
                                           : (const __nv_bfloat16*)g_w2h;
    const __nv_bfloat16* btl = (WSEL == 1) ? (const __nv_bfloat16*)g_w1l
                                           : (const __nv_bfloat16*)g_w2l;
    const __nv_bfloat16* ah = (const __nv_bfloat16*)g_ahi;
    const __nv_bfloat16* al = (const __nv_bfloat16*)g_alo;

    unsigned sb = smem_u32(smem);
    int tid  = threadIdx.x;
    int lane = tid & 31;
    int wid  = tid >> 5;
    int wm   = wid >> 1;            // 0..1 -> 64 rows each
    int wn   = wid & 1;             // 0..1 -> 64 cols each
    int bm = blockIdx.y * 128;
    int bn = blockIdx.x * 128;

    // ldmatrix lane address components
    int a_row = ((lane >> 3) & 1) * 8 + (lane & 7);  // tile row select
    int a_colb = ((lane >> 4) ? 16 : 0);             // tile col half (bytes)
    int b_row = (lane >> 4) * 8 + (lane & 7);
    int b_colb = ((lane >> 3) & 1) * 16;

    float acc[4][8][4];
    #pragma unroll
    for (int i = 0; i < 4; i++)
        #pragma unroll
        for (int j = 0; j < 8; j++)
            #pragma unroll
            for (int q = 0; q < 4; q++) acc[i][j][q] = 0.f;

    // ---- G2S stage issue (cp.async)
    auto issue = [&](int st, int kc) {
        unsigned base = sb + (unsigned)st * STG;
        #pragma unroll
        for (int i = 0; i < 4; i++) {
            int v = tid + i * 128;
            int row = v >> 2;
            int cb  = (v & 3) * 16;                  // byte col within 64B row
            int gr  = bm + row;
            int sz  = (gr < N_NODES_) ? 16 : 0;
            size_t aoff = ((size_t)gr * DIM + kc) * 2 + cb;
            cp16(base + OFF_AH + row * 80 + cb, (const char*)ah + aoff, sz);
            cp16(base + OFF_AL + row * 80 + cb, (const char*)al + aoff, sz);
            size_t boff = ((size_t)(bn + row) * DIM + kc) * 2 + cb;
            cp16(base + OFF_BH + row * 80 + cb, (const char*)bth + boff, 16);
            cp16(base + OFF_BL + row * 80 + cb, (const char*)btl + boff, 16);
        }
        asm volatile("cp.async.commit_group;" ::: "memory");
    };

    issue(0, 0);
    issue(1, 32);

    for (int ks = 0; ks < NK; ks++) {
        if (ks == NK - 1) asm volatile("cp.async.wait_group 0;" ::: "memory");
        else              asm volatile("cp.async.wait_group 1;" ::: "memory");
        __syncthreads();

        unsigned st = sb + (unsigned)(ks & 1) * STG;
        #pragma unroll
        for (int kf = 0; kf < 2; kf++) {
            unsigned aH[4][4], aL[4][4];
            #pragma unroll
            for (int mf = 0; mf < 4; mf++) {
                unsigned ra = (unsigned)(wm * 64 + mf * 16 + a_row) * 80
                            + (unsigned)(kf * 32 + a_colb);
                ldsm_x4(aH[mf], st + OFF_AH + ra);
                ldsm_x4(aL[mf], st + OFF_AL + ra);
            }
            #pragma unroll
            for (int nfp = 0; nfp < 4; nfp++) {
                unsigned rb = (unsigned)(wn * 64 + nfp * 16 + b_row) * 80
                            + (unsigned)(kf * 32 + b_colb);
                unsigned bH[4], bL[4];
                ldsm_x4(bH, st + OFF_BH + rb);
                ldsm_x4(bL, st + OFF_BL + rb);
                #pragma unroll
                for (int mf = 0; mf < 4; mf++) {
                    mma16816(acc[mf][2 * nfp + 0], aH[mf], bH + 0);
                    mma16816(acc[mf][2 * nfp + 1], aH[mf], bH + 2);
                    mma16816(acc[mf][2 * nfp + 0], aH[mf], bL + 0);
                    mma16816(acc[mf][2 * nfp + 1], aH[mf], bL + 2);
                    mma16816(acc[mf][2 * nfp + 0], aL[mf], bH + 0);
                    mma16816(acc[mf][2 * nfp + 1], aL[mf], bH + 2);
                }
            }
        }
        __syncthreads();
        if (ks + 2 < NK) issue(ks & 1, (ks + 2) * 32);
    }

    // ---- epilogue
    int gr0 = bm + wm * 64 + (lane >> 2);
    int gc0 = bn + wn * 64 + 2 * (lane & 3);
    #pragma unroll
    for (int mf = 0; mf < 4; mf++) {
        int r0 = gr0 + mf * 16;
        #pragma unroll
        for (int nf = 0; nf < 8; nf++) {
            int c = gc0 + nf * 8;
            if (r0 < N_NODES_)
                *(float2*)(g_h + (size_t)r0 * DIM + c) =
                    make_float2(acc[mf][nf][0], acc[mf][nf][1]);
            if (r0 + 8 < N_NODES_)
                *(float2*)(g_h + (size_t)(r0 + 8) * DIM + c) =
                    make_float2(acc[mf][nf][2], acc[mf][nf][3]);
        }
    }
}

// ---------------- fused gather conv: g_y = propagate(g_h) + b (opt ReLU) ------
template <bool RELU>
__global__ __launch_bounds__(256)
void gather_kernel(const float* __restrict__ b) {
    const float* __restrict__ h = (const float*)g_h;
    float* __restrict__ y = (float*)g_y;

    int node = blockIdx.x * 8 + (threadIdx.x >> 5);
    int lane = threadIdx.x & 31;
    if (node >= N_NODES_) return;

    float dn = g_dis[node];
    float self_w = dn * dn;
    const float4* hn = (const float4*)(h + (size_t)node * DIM);

    float4 acc[4];
    #pragma unroll
    for (int c = 0; c < 4; c++) {
        float4 v = hn[lane + 32 * c];
        acc[c] = make_float4(v.x * self_w, v.y * self_w, v.z * self_w, v.w * self_w);
    }

    int beg = g_off[node];
    int end = beg + g_deg[node] - 1;
    for (int e = beg; e < end; e++) {
        int s   = g_csrc[e];
        float w = g_cnorm[e];
        const float4* hs = (const float4*)(h + (size_t)s * DIM);
        #pragma unroll
        for (int c = 0; c < 4; c++) {
            float4 v = hs[lane + 32 * c];
            acc[c].x = fmaf(v.x, w, acc[c].x);
            acc[c].y = fmaf(v.y, w, acc[c].y);
            acc[c].z = fmaf(v.z, w, acc[c].z);
            acc[c].w = fmaf(v.w, w, acc[c].w);
        }
    }

    float4* yn = (float4*)(y + (size_t)node * DIM);
    const float4* bb = (const float4*)b;
    #pragma unroll
    for (int c = 0; c < 4; c++) {
        float4 bv = bb[lane + 32 * c];
        float4 r;
        r.x = acc[c].x + bv.x; r.y = acc[c].y + bv.y;
        r.z = acc[c].z + bv.z; r.w = acc[c].w + bv.w;
        if (RELU) {
            r.x = fmaxf(r.x, 0.f); r.y = fmaxf(r.y, 0.f);
            r.z = fmaxf(r.z, 0.f); r.w = fmaxf(r.w, 0.f);
        }
        yn[lane + 32 * c] = r;
    }
}

// ---------------- global mean pool via sorted-batch segments -----------------
__global__ __launch_bounds__(512)
void pool_kernel() {
    int g = blockIdx.x;
    int j = threadIdx.x;
    int beg = g_goff[g];
    int cnt = g_cnt[g];
    float s = 0.f;
    for (int r = beg; r < beg + cnt; r++)
        s += g_y[(size_t)r * DIM + j];
    g_pool[(size_t)g * DIM + j] = s / fmaxf((float)cnt, 1.f);
}

// ---------------- final: out[g] = pool[g] @ Wlin + blin ----------------------
__global__ __launch_bounds__(512)
void final_gemm(const float* __restrict__ Wlin, const float* __restrict__ blin,
                float* __restrict__ out) {
    int g = blockIdx.x;
    int j = threadIdx.x;
    __shared__ float sp[DIM];
    sp[j] = g_pool[(size_t)g * DIM + j];
    __syncthreads();
    float acc = blin[j];
    #pragma unroll 8
    for (int k = 0; k < DIM; k++)
        acc = fmaf(sp[k], __ldg(&Wlin[(size_t)k * DIM + j]), acc);
    out[(size_t)g * DIM + j] = acc;
}

// ---------------- launcher ---------------------------------------------------
extern "C" void kernel_launch(void* const* d_in, const int* in_sizes, int n_in,
                              void* d_out, int out_size) {
    const float* x    = (const float*)d_in[0];
    const void*  ei   = d_in[1];
    const void*  batch= d_in[2];
    const float* W1   = (const float*)d_in[3];
    const float* b1   = (const float*)d_in[4];
    const float* W2   = (const float*)d_in[5];
    const float* b2   = (const float*)d_in[6];
    const float* Wlin = (const float*)d_in[7];
    const float* blin = (const float*)d_in[8];
    float* out = (float*)d_out;

    static int smem_set = 0;
    if (!smem_set) {
        cudaFuncSetAttribute(hmma_gemm<1>, cudaFuncAttributeMaxDynamicSharedMemorySize, SMEM_HMMA);
        cudaFuncSetAttribute(hmma_gemm<2>, cudaFuncAttributeMaxDynamicSharedMemorySize, SMEM_HMMA);
        smem_set = 1;
    }

    detect_kernel<<<1, 32>>>((const int*)ei);
    init_kernel<<<(N_NODES_ + 255) / 256, 256>>>();
    col_stats<<<(N_NODES_ + ROWS_PER_BLOCK - 1) / ROWS_PER_BLOCK, 256>>>(x);
    finalize_stats<<<2, 256>>>();
    degree_kernel<<<(N_EDGES_ + 255) / 256, 256>>>(ei, batch);
    dis_kernel<<<(N_NODES_ + 255) / 256, 256>>>();
    scan_kernel<<<1, 1024>>>();
    goff_kernel<<<1, 32>>>();
    fill_kernel<<<(N_EDGES_ + 255) / 256, 256>>>(ei);
    convW<<<2 * DIM * DIM / 256, 256>>>(W1, W2);

    dim3 mgrid(4, (N_NODES_ + 127) / 128);   // 4 N-tiles x 157 M-tiles

    // ---- conv1
    convA<true><<<(N_NODES_ * DIM / 4 + 255) / 256, 256>>>(x);
    hmma_gemm<1><<<mgrid, 128, SMEM_HMMA>>>();
    gather_kernel<true><<<(N_NODES_ + 7) / 8, 256>>>(b1);

    // ---- conv2
    convA<false><<<(N_NODES_ * DIM / 4 + 255) / 256, 256>>>(nullptr);
    hmma_gemm<2><<<mgrid, 128, SMEM_HMMA>>>();
    gather_kernel<false><<<(N_NODES_ + 7) / 8, 256>>>(b2);

    // ---- pool + final linear
    pool_kernel<<<N_GRAPHS_, 512>>>();
    final_gemm<<<N_GRAPHS_, 512>>>(Wlin, blin, out);
}